// round 16
// baseline (speedup 1.0000x reference)
#include <cuda_runtime.h>
#include <cuda_fp16.h>
#include <cstdint>

#define NN 100000
#define EE 1600000
#define EPP 200000
#define ST2 68   // smem row stride in words: 64 data + 4 pad (68 mod 32 == 4)

// ---------------- scratch (static device globals; no allocation) ------------
// Zero-init at module load covers call #1; k_reset re-zeroes g_deg each call.
__device__ int      g_deg[NN];
__device__ int      g_off[NN + 1];
__device__ int      g_cur[NN];
__device__ int      g_adj[EE];
__device__ float    g_dinv[NN];
__device__ __half   g_hs1[(size_t)NN * 128]; // dinv[r]*(x@W1)  (fp16)
__device__ __half   g_a1h[(size_t)NN * 128]; // aggregated layer-1 (fp16)
__device__ __half   g_hs2[(size_t)NN * 64];  // dinv[r]*relu(a1+b1)@W2 (fp16)
__device__ __half   g_z  [(size_t)NN * 64];  // final embeddings (fp16)
__device__ int      g_bsum[256];
// packed weights: [n][k2] half2 = (W[2k2][n], W[2k2+1][n])
__device__ unsigned g_W1p[128 * 64];
__device__ unsigned g_W2p[64 * 64];

// ---------------- fp16 helpers ----------------------------------------------
__device__ __forceinline__ unsigned f2h2(float a, float b) {
    __half2 h = __floats2half2_rn(a, b);
    return *reinterpret_cast<unsigned*>(&h);
}
__device__ __forceinline__ float2 h2f2(unsigned u) {
    __half2 h = *reinterpret_cast<__half2*>(&u);
    return __half22float2(h);
}
__device__ __forceinline__ unsigned hadd2u(unsigned a, unsigned b) {
    __half2 r = __hadd2(*reinterpret_cast<__half2*>(&a), *reinterpret_cast<__half2*>(&b));
    return *reinterpret_cast<unsigned*>(&r);
}

__device__ __forceinline__ void mmaf16(float* c, const unsigned* a, unsigned b0, unsigned b1) {
    asm("mma.sync.aligned.m16n8k16.row.col.f32.f16.f16.f32 "
        "{%0,%1,%2,%3}, {%4,%5,%6,%7}, {%8,%9}, {%0,%1,%2,%3};"
        : "+f"(c[0]), "+f"(c[1]), "+f"(c[2]), "+f"(c[3])
        : "r"(a[0]), "r"(a[1]), "r"(a[2]), "r"(a[3]), "r"(b0), "r"(b1));
}

__device__ __forceinline__ void ldsm4(unsigned* r, unsigned addr) {
    asm volatile("ldmatrix.sync.aligned.m8n8.x4.shared.b16 {%0,%1,%2,%3}, [%4];"
        : "=r"(r[0]), "=r"(r[1]), "=r"(r[2]), "=r"(r[3]) : "r"(addr));
}

// ---------------- degree / CSR build ----------------------------------------
__global__ void k_count(const int* __restrict__ dst) {
    int e = (blockIdx.x * blockDim.x + threadIdx.x) * 4;
    if (e < EE) {
        int4 d = *(const int4*)(dst + e);
        atomicAdd(&g_deg[d.x], 1);
        atomicAdd(&g_deg[d.y], 1);
        atomicAdd(&g_deg[d.z], 1);
        atomicAdd(&g_deg[d.w], 1);
    }
}

// fused: block scan of deg + dinv computation
__global__ void k_scanA() {
    __shared__ int s[512];
    int t = threadIdx.x;
    int idx = blockIdx.x * 512 + t;
    int v = (idx < NN) ? g_deg[idx] : 0;
    if (idx < NN) g_dinv[idx] = rsqrtf((float)(v + 1));  // +1 self loop
    s[t] = v;
    __syncthreads();
#pragma unroll
    for (int o = 1; o < 512; o <<= 1) {
        int x = (t >= o) ? s[t - o] : 0;
        __syncthreads();
        s[t] += x;
        __syncthreads();
    }
    if (idx < NN) g_off[idx] = s[t] - v;
    if (t == 511) g_bsum[blockIdx.x] = s[511];
}

// fused scan2+scan3: each block reduces its g_bsum prefix, then offsets
__global__ void k_scan3() {
    __shared__ int s[512];
    int t = threadIdx.x;
    s[t] = (t < (int)blockIdx.x) ? g_bsum[t] : 0;   // bid <= 195 < 512
    __syncthreads();
#pragma unroll
    for (int o = 256; o > 0; o >>= 1) {
        if (t < o) s[t] += s[t + o];
        __syncthreads();
    }
    int boff = s[0];
    int idx = blockIdx.x * 512 + t;
    if (idx < NN) {
        int val = g_off[idx] + boff;
        g_off[idx] = val;
        g_cur[idx] = val;
        if (idx == 0) g_off[NN] = EE;
    }
}

__global__ void k_fill(const int* __restrict__ src, const int* __restrict__ dst) {
    int e = (blockIdx.x * blockDim.x + threadIdx.x) * 4;
    if (e < EE) {
        int4 d = *(const int4*)(dst + e);
        int4 sv = *(const int4*)(src + e);
        g_adj[atomicAdd(&g_cur[d.x], 1)] = sv.x;
        g_adj[atomicAdd(&g_cur[d.y], 1)] = sv.y;
        g_adj[atomicAdd(&g_cur[d.z], 1)] = sv.z;
        g_adj[atomicAdd(&g_cur[d.w], 1)] = sv.w;
    }
}

// zero g_deg for the NEXT call (s2, after ev1; joined via evR before decode)
__global__ void k_reset() {
    int i = blockIdx.x * blockDim.x + threadIdx.x;
    if (i < NN) g_deg[i] = 0;
}

// ---------------- weight fp16 transpose-pack ---------------------------------
__global__ void k_wprep(const float* __restrict__ W1, const float* __restrict__ W2) {
    int i = blockIdx.x * blockDim.x + threadIdx.x;
    if (i < 128 * 64) {
        int n = i >> 6, k2 = i & 63;
        g_W1p[i] = f2h2(W1[(2 * k2) * 128 + n], W1[(2 * k2 + 1) * 128 + n]);
    } else if (i < 128 * 64 + 64 * 64) {
        int j = i - 128 * 64;
        int n = j >> 6, k2 = j & 63;
        g_W2p[j] = f2h2(W2[(2 * k2) * 64 + n], W2[(2 * k2 + 1) * 64 + n]);
    }
}

// ---------------- tensor-core GEMM, SINGLE full-K stage, dinv epilogue -------
// LAYER 1: hs1[NN,128] = dinv[r] * (fp16(x) @ fp16(W1)),  MT=64,  NOUT=128
// LAYER 2: hs2[NN,64]  = dinv[r] * (relu(a1h+b1) @ W2),   MT=128, NOUT=64
// 256 threads = 8 warps. Full K=128 staged at once (row = 64 half2 words + 4
// pad); ONE __syncthreads, then 8 k16 mma rounds. Dyn smem (MT+NOUT)*ST2*4.
template<int LAYER>
__global__ __launch_bounds__(256) void k_tc(const float* __restrict__ Xsrc,
                                            const float* __restrict__ bias) {
    constexpr int MT   = (LAYER == 1) ? 64 : 128;
    constexpr int NOUT = (LAYER == 1) ? 128 : 64;

    const unsigned* Wp  = (LAYER == 1) ? g_W1p : g_W2p;
    __half*         Out = (LAYER == 1) ? g_hs1 : g_hs2;

    extern __shared__ unsigned smem_u[];
    unsigned* Ah = smem_u;                 // MT * ST2 words
    unsigned* Bh = smem_u + MT * ST2;      // NOUT * ST2 words

    const int tid  = threadIdx.x;
    const int lane = tid & 31;
    const int wid  = tid >> 5;
    const int g    = lane >> 2;
    const int t4   = lane & 3;
    const int row0 = blockIdx.x * MT;
    const int warpM = (LAYER == 1) ? (wid >> 1) * 16 : wid * 16;
    const int n0    = (LAYER == 1) ? (wid & 1) * 64 : 0;

    const unsigned sAh = (unsigned)__cvta_generic_to_shared(Ah);
    const unsigned sBh = (unsigned)__cvta_generic_to_shared(Bh);
    const int l7 = lane & 7;
    const int r8 = (lane >> 3) & 1;
    const int w4 = (lane >> 4) * 4;
    const unsigned aAddr = sAh + (unsigned)(((warpM + l7 + r8 * 8) * ST2 + w4) * 4);
    unsigned bAddr[4];
    const int bw4 = ((lane >> 3) & 1) * 4;
    const int bn8 = (lane >= 16) ? 8 : 0;
#pragma unroll
    for (int nn = 0; nn < 4; nn++) {
        int nrow = n0 + nn * 16 + l7 + bn8;
        bAddr[nn] = sBh + (unsigned)((nrow * ST2 + bw4) * 4);
    }

    // ---- stage A: MT rows x 64 words --------------------------------------
    if (LAYER == 1) {
#pragma unroll
        for (int j = 0; j < MT / 8; j++) {
            int idx = tid + 256 * j;            // float4 slots (32/row)
            int r = idx >> 5, c4 = idx & 31;
            int gr = row0 + r;
            float4 v = {0.f, 0.f, 0.f, 0.f};
            if (gr < NN)
                v = ((const float4*)(Xsrc + (size_t)gr * 128))[c4];
            *(uint2*)&Ah[r * ST2 + c4 * 2] =
                make_uint2(f2h2(v.x, v.y), f2h2(v.z, v.w));
        }
    } else {
#pragma unroll
        for (int j = 0; j < MT / 8; j++) {
            int idx = tid + 256 * j;            // uint2 slots (32/row)
            int r = idx >> 5, u2 = idx & 31;
            int gr = row0 + r;
            uint2 u = {0, 0};
            if (gr < NN) {
                u = ((const uint2*)(g_a1h + (size_t)gr * 128))[u2];
                float2 ba = ((const float2*)bias)[u2 * 2];
                float2 bb = ((const float2*)bias)[u2 * 2 + 1];
                float2 f0 = h2f2(u.x), f1 = h2f2(u.y);
                u.x = f2h2(fmaxf(f0.x + ba.x, 0.f), fmaxf(f0.y + ba.y, 0.f));
                u.y = f2h2(fmaxf(f1.x + bb.x, 0.f), fmaxf(f1.y + bb.y, 0.f));
            }
            *(uint2*)&Ah[r * ST2 + u2 * 2] = u;
        }
    }
    // ---- stage B: NOUT rows x 64 words ------------------------------------
#pragma unroll
    for (int j = 0; j < NOUT / 8; j++) {
        int idx = tid + 256 * j;                // uint2 slots (32/row)
        int n = idx >> 5, u2 = idx & 31;
        *(uint2*)&Bh[n * ST2 + u2 * 2] = *(const uint2*)&Wp[n * 64 + u2 * 2];
    }
    __syncthreads();

    // ---- accumulate: 8 k16 rounds, no further syncs -----------------------
    float acc[8][4];
#pragma unroll
    for (int ni = 0; ni < 8; ni++)
#pragma unroll
        for (int q = 0; q < 4; q++) acc[ni][q] = 0.f;

#pragma unroll
    for (int kc = 0; kc < 8; kc++) {
        const unsigned koff = kc * 32;          // 8 words = 32 bytes
        unsigned ah[4];
        ldsm4(ah, aAddr + koff);
#pragma unroll
        for (int nn = 0; nn < 4; nn++) {
            unsigned bh[4];
            ldsm4(bh, bAddr[nn] + koff);
#pragma unroll
            for (int p = 0; p < 2; p++) {
                int ni = nn * 2 + p;
                mmaf16(acc[ni], ah, bh[p * 2], bh[p * 2 + 1]);
            }
        }
    }

    // ---- epilogue: dinv[r] prescale, fp16 output --------------------------
#pragma unroll
    for (int ni = 0; ni < 8; ni++) {
        int r  = row0 + warpM + g;
        int cc = n0 + ni * 8 + 2 * t4;
        if (r < NN) {
            float s = g_dinv[r];
            __half2 o = __floats2half2_rn(acc[ni][0] * s, acc[ni][1] * s);
            *((__half2*)(Out + (size_t)r * NOUT + cc)) = o;
        }
        if (r + 8 < NN) {
            float s = g_dinv[r + 8];
            __half2 o = __floats2half2_rn(acc[ni][2] * s, acc[ni][3] * s);
            *((__half2*)(Out + (size_t)(r + 8) * NOUT + cc)) = o;
        }
    }
}

// ---------------- AGG 1: a1h[d] = dd * sum of prescaled rows -----------------
// 8-edge batches, fp16 pairwise-tree (HADD2) then fp32 merge.
__global__ void k_agg1() {
    int gw = (blockIdx.x * blockDim.x + threadIdx.x) >> 5;
    if (gw >= NN) return;
    int lane = threadIdx.x & 31;
    int o0 = g_off[gw], o1 = g_off[gw + 1];
    const uint2* base = (const uint2*)g_hs1;
    float dd = g_dinv[gw];

    uint2 sv = base[(size_t)gw * 32 + lane];
    float2 p0 = h2f2(sv.x), p1 = h2f2(sv.y);
    float a0 = p0.x, a1 = p0.y, a2 = p1.x, a3 = p1.y;

    int i = o0;
    for (; i + 8 <= o1; i += 8) {
        int s0 = g_adj[i],     s1 = g_adj[i + 1], s2 = g_adj[i + 2], s3 = g_adj[i + 3];
        int s4 = g_adj[i + 4], s5 = g_adj[i + 5], s6 = g_adj[i + 6], s7 = g_adj[i + 7];
        uint2 v0 = base[(size_t)s0 * 32 + lane];
        uint2 v1 = base[(size_t)s1 * 32 + lane];
        uint2 v2 = base[(size_t)s2 * 32 + lane];
        uint2 v3 = base[(size_t)s3 * 32 + lane];
        uint2 v4 = base[(size_t)s4 * 32 + lane];
        uint2 v5 = base[(size_t)s5 * 32 + lane];
        uint2 v6 = base[(size_t)s6 * 32 + lane];
        uint2 v7 = base[(size_t)s7 * 32 + lane];
        unsigned tx = hadd2u(hadd2u(hadd2u(v0.x, v1.x), hadd2u(v2.x, v3.x)),
                             hadd2u(hadd2u(v4.x, v5.x), hadd2u(v6.x, v7.x)));
        unsigned ty = hadd2u(hadd2u(hadd2u(v0.y, v1.y), hadd2u(v2.y, v3.y)),
                             hadd2u(hadd2u(v4.y, v5.y), hadd2u(v6.y, v7.y)));
        float2 qx = h2f2(tx), qy = h2f2(ty);
        a0 += qx.x; a1 += qx.y; a2 += qy.x; a3 += qy.y;
    }
    for (; i < o1; i++) {
        int s = g_adj[i];
        uint2 v = base[(size_t)s * 32 + lane];
        float2 q0 = h2f2(v.x), q1 = h2f2(v.y);
        a0 += q0.x; a1 += q0.y; a2 += q1.x; a3 += q1.y;
    }
    uint2 o;
    o.x = f2h2(a0 * dd, a1 * dd);
    o.y = f2h2(a2 * dd, a3 * dd);
    ((uint2*)g_a1h)[(size_t)gw * 32 + lane] = o;
}

// ---------------- AGG 2: z[d] = dd * sum of prescaled hs2 rows + b2 ----------
__global__ void k_agg2(const float* __restrict__ b2) {
    int gw = (blockIdx.x * blockDim.x + threadIdx.x) >> 5;
    if (gw >= NN) return;
    int lane = threadIdx.x & 31;
    int o0 = g_off[gw], o1 = g_off[gw + 1];
    const unsigned* base = (const unsigned*)g_hs2;
    float dd = g_dinv[gw];

    float2 p = h2f2(base[(size_t)gw * 32 + lane]);
    float a0 = p.x, a1 = p.y;

    int i = o0;
    for (; i + 8 <= o1; i += 8) {
        int s0 = g_adj[i],     s1 = g_adj[i + 1], s2 = g_adj[i + 2], s3 = g_adj[i + 3];
        int s4 = g_adj[i + 4], s5 = g_adj[i + 5], s6 = g_adj[i + 6], s7 = g_adj[i + 7];
        unsigned v0 = base[(size_t)s0 * 32 + lane];
        unsigned v1 = base[(size_t)s1 * 32 + lane];
        unsigned v2 = base[(size_t)s2 * 32 + lane];
        unsigned v3 = base[(size_t)s3 * 32 + lane];
        unsigned v4 = base[(size_t)s4 * 32 + lane];
        unsigned v5 = base[(size_t)s5 * 32 + lane];
        unsigned v6 = base[(size_t)s6 * 32 + lane];
        unsigned v7 = base[(size_t)s7 * 32 + lane];
        unsigned t = hadd2u(hadd2u(hadd2u(v0, v1), hadd2u(v2, v3)),
                            hadd2u(hadd2u(v4, v5), hadd2u(v6, v7)));
        float2 q = h2f2(t);
        a0 += q.x; a1 += q.y;
    }
    for (; i < o1; i++) {
        float2 v = h2f2(base[(size_t)g_adj[i] * 32 + lane]);
        a0 += v.x; a1 += v.y;
    }
    float2 b = ((const float2*)b2)[lane];
    __half2 oz = __floats2half2_rn(a0 * dd + b.x, a1 * dd + b.y);
    ((__half2*)g_z)[(size_t)gw * 32 + lane] = oz;
}

// ---------------- decode: 2 edges per warp (fp16 z gather) -------------------
__global__ void k_decode(const int* __restrict__ pos, const int* __restrict__ neg,
                         float* __restrict__ out) {
    int w = (blockIdx.x * blockDim.x + threadIdx.x) >> 5;
    int e0 = w * 2;
    if (e0 >= 2 * EPP) return;                 // e0 even => e0+1 < 2*EPP too
    int lane = threadIdx.x & 31;
    int a0, b0, a1, b1;
    {
        int e = e0;
        if (e < EPP) { a0 = pos[e]; b0 = pos[EPP + e]; }
        else         { a0 = neg[e - EPP]; b0 = neg[e]; }   // neg[EPP + (e-EPP)]
        e = e0 + 1;
        if (e < EPP) { a1 = pos[e]; b1 = pos[EPP + e]; }
        else         { a1 = neg[e - EPP]; b1 = neg[e]; }
    }
    const unsigned* Z = (const unsigned*)g_z;
    unsigned za0 = Z[(size_t)a0 * 32 + lane];
    unsigned zb0 = Z[(size_t)b0 * 32 + lane];
    unsigned za1 = Z[(size_t)a1 * 32 + lane];
    unsigned zb1 = Z[(size_t)b1 * 32 + lane];
    float2 xa0 = h2f2(za0), xb0 = h2f2(zb0);
    float2 xa1 = h2f2(za1), xb1 = h2f2(zb1);
    float p0 = xa0.x * xb0.x + xa0.y * xb0.y;
    float p1 = xa1.x * xb1.x + xa1.y * xb1.y;
#pragma unroll
    for (int o = 16; o > 0; o >>= 1) {
        p0 += __shfl_xor_sync(0xFFFFFFFFu, p0, o);
        p1 += __shfl_xor_sync(0xFFFFFFFFu, p1, o);
    }
    if (lane == 0) { out[e0] = p0; out[e0 + 1] = p1; }
}

// ---------------- launch ------------------------------------------------------
extern "C" void kernel_launch(void* const* d_in, const int* in_sizes, int n_in,
                              void* d_out, int out_size) {
    const float* x   = (const float*)d_in[0];
    const int*   ei  = (const int*)  d_in[1];
    const int*   pos = (const int*)  d_in[2];
    const int*   neg = (const int*)  d_in[3];
    const float* W1  = (const float*)d_in[4];
    const float* b1  = (const float*)d_in[5];
    const float* W2  = (const float*)d_in[6];
    const float* b2  = (const float*)d_in[7];
    float* out = (float*)d_out;

    const int* src = ei;
    const int* dst = ei + EE;
    const int nb_scan = (NN + 511) / 512;  // 196

    const int SMEM1 = (64 + 128) * ST2 * 4;    // 52224 bytes
    const int SMEM2 = (128 + 64) * ST2 * 4;    // 52224 bytes

    static cudaStream_t s2 = nullptr;
    static cudaEvent_t ev0 = nullptr, evD = nullptr, ev1 = nullptr, evR = nullptr;
    if (!s2) {
        cudaStreamCreateWithFlags(&s2, cudaStreamNonBlocking);
        cudaEventCreateWithFlags(&ev0, cudaEventDisableTiming);
        cudaEventCreateWithFlags(&evD, cudaEventDisableTiming);
        cudaEventCreateWithFlags(&ev1, cudaEventDisableTiming);
        cudaEventCreateWithFlags(&evR, cudaEventDisableTiming);
        cudaFuncSetAttribute(k_tc<1>, cudaFuncAttributeMaxDynamicSharedMemorySize, SMEM1);
        cudaFuncSetAttribute(k_tc<2>, cudaFuncAttributeMaxDynamicSharedMemorySize, SMEM2);
    }

    // fork: weight prep runs on s2 from the start
    cudaEventRecord(ev0, 0);
    cudaStreamWaitEvent(s2, ev0, 0);

    k_count<<<(EE / 4 + 255) / 256, 256>>>(dst);                // main
    k_wprep<<<48, 256, 0, s2>>>(W1, W2);                        // s2
    k_scanA<<<nb_scan, 512>>>();                                // main (scan+dinv)
    cudaEventRecord(evD, 0);                                    // dinv ready

    // s2: tc1 (reads dinv in epilogue -> needs evD); ev1 BEFORE reset
    cudaStreamWaitEvent(s2, evD, 0);
    k_tc<1><<<(NN + 63) / 64, 256, SMEM1, s2>>>(x, nullptr);    // s2
    cudaEventRecord(ev1, s2);
    k_reset<<<(NN + 255) / 256, 256, 0, s2>>>();                // s2 (off join path)
    cudaEventRecord(evR, s2);                                   // for final join

    k_scan3<<<nb_scan, 512>>>();                                // main (fused scan2+3)
    k_fill<<<(EE / 4 + 255) / 256, 256>>>(src, dst);            // main

    // join: agg1 needs CSR (main, in-order) + hs1 (s2)
    cudaStreamWaitEvent(0, ev1, 0);

    k_agg1<<<(NN * 32 + 255) / 256, 256>>>();
    k_tc<2><<<(NN + 127) / 128, 256, SMEM2>>>(nullptr, b1);
    k_agg2<<<(NN * 32 + 255) / 256, 256>>>(b2);
    // join s2 fully before the last launch (graph capture requires no
    // unjoined forked work; reset ended long ago so this edge is free)
    cudaStreamWaitEvent(0, evR, 0);
    // 200k warps (2 edges each) = 6.4M threads = 25000 blocks
    k_decode<<<(EPP * 32 + 255) / 256, 256>>>(pos, neg, out);
}

// round 17
// speedup vs baseline: 1.1003x; 1.1003x over previous
#include <cuda_runtime.h>
#include <cuda_fp16.h>
#include <cstdint>

#define NN 100000
#define EE 1600000
#define EPP 200000
#define ST2 68   // smem row stride in words: 64 data + 4 pad (68 mod 32 == 4)

// ---------------- scratch (static device globals; no allocation) ------------
// Zero-init at module load covers call #1; k_reset re-zeroes g_deg each call.
__device__ int      g_deg[NN];
__device__ int      g_off[NN + 1];
__device__ int      g_cur[NN];
__device__ int      g_adj[EE];
__device__ float    g_dinv[NN];
__device__ __half   g_hs1[(size_t)NN * 128]; // dinv[r]*(x@W1)  (fp16)
__device__ __half   g_a1h[(size_t)NN * 128]; // aggregated layer-1 (fp16)
__device__ __half   g_hs2[(size_t)NN * 64];  // dinv[r]*relu(a1+b1)@W2 (fp16)
__device__ __half   g_z  [(size_t)NN * 64];  // final embeddings (fp16)
__device__ int      g_bsum[256];
// packed weights: [n][k2] half2 = (W[2k2][n], W[2k2+1][n])
__device__ unsigned g_W1p[128 * 64];
__device__ unsigned g_W2p[64 * 64];

// ---------------- fp16 helpers ----------------------------------------------
__device__ __forceinline__ unsigned f2h2(float a, float b) {
    __half2 h = __floats2half2_rn(a, b);
    return *reinterpret_cast<unsigned*>(&h);
}
__device__ __forceinline__ float2 h2f2(unsigned u) {
    __half2 h = *reinterpret_cast<__half2*>(&u);
    return __half22float2(h);
}
__device__ __forceinline__ unsigned hadd2u(unsigned a, unsigned b) {
    __half2 r = __hadd2(*reinterpret_cast<__half2*>(&a), *reinterpret_cast<__half2*>(&b));
    return *reinterpret_cast<unsigned*>(&r);
}

__device__ __forceinline__ void mmaf16(float* c, const unsigned* a, unsigned b0, unsigned b1) {
    asm("mma.sync.aligned.m16n8k16.row.col.f32.f16.f16.f32 "
        "{%0,%1,%2,%3}, {%4,%5,%6,%7}, {%8,%9}, {%0,%1,%2,%3};"
        : "+f"(c[0]), "+f"(c[1]), "+f"(c[2]), "+f"(c[3])
        : "r"(a[0]), "r"(a[1]), "r"(a[2]), "r"(a[3]), "r"(b0), "r"(b1));
}

__device__ __forceinline__ void ldsm4(unsigned* r, unsigned addr) {
    asm volatile("ldmatrix.sync.aligned.m8n8.x4.shared.b16 {%0,%1,%2,%3}, [%4];"
        : "=r"(r[0]), "=r"(r[1]), "=r"(r[2]), "=r"(r[3]) : "r"(addr));
}

// ---------------- degree / CSR build ----------------------------------------
__global__ void k_count(const int* __restrict__ dst) {
    int e = (blockIdx.x * blockDim.x + threadIdx.x) * 4;
    if (e < EE) {
        int4 d = *(const int4*)(dst + e);
        atomicAdd(&g_deg[d.x], 1);
        atomicAdd(&g_deg[d.y], 1);
        atomicAdd(&g_deg[d.z], 1);
        atomicAdd(&g_deg[d.w], 1);
    }
}

// fused: block scan of deg + dinv computation
__global__ void k_scanA() {
    __shared__ int s[512];
    int t = threadIdx.x;
    int idx = blockIdx.x * 512 + t;
    int v = (idx < NN) ? g_deg[idx] : 0;
    if (idx < NN) g_dinv[idx] = rsqrtf((float)(v + 1));  // +1 self loop
    s[t] = v;
    __syncthreads();
#pragma unroll
    for (int o = 1; o < 512; o <<= 1) {
        int x = (t >= o) ? s[t - o] : 0;
        __syncthreads();
        s[t] += x;
        __syncthreads();
    }
    if (idx < NN) g_off[idx] = s[t] - v;
    if (t == 511) g_bsum[blockIdx.x] = s[511];
}

// fused scan2+scan3: each block reduces its g_bsum prefix, then offsets
__global__ void k_scan3() {
    __shared__ int s[512];
    int t = threadIdx.x;
    s[t] = (t < (int)blockIdx.x) ? g_bsum[t] : 0;   // bid <= 195 < 512
    __syncthreads();
#pragma unroll
    for (int o = 256; o > 0; o >>= 1) {
        if (t < o) s[t] += s[t + o];
        __syncthreads();
    }
    int boff = s[0];
    int idx = blockIdx.x * 512 + t;
    if (idx < NN) {
        int val = g_off[idx] + boff;
        g_off[idx] = val;
        g_cur[idx] = val;
        if (idx == 0) g_off[NN] = EE;
    }
}

__global__ void k_fill(const int* __restrict__ src, const int* __restrict__ dst) {
    int e = (blockIdx.x * blockDim.x + threadIdx.x) * 4;
    if (e < EE) {
        int4 d = *(const int4*)(dst + e);
        int4 sv = *(const int4*)(src + e);
        g_adj[atomicAdd(&g_cur[d.x], 1)] = sv.x;
        g_adj[atomicAdd(&g_cur[d.y], 1)] = sv.y;
        g_adj[atomicAdd(&g_cur[d.z], 1)] = sv.z;
        g_adj[atomicAdd(&g_cur[d.w], 1)] = sv.w;
    }
}

// zero g_deg for the NEXT call (s2, after ev1; joined via evR before decode)
__global__ void k_reset() {
    int i = blockIdx.x * blockDim.x + threadIdx.x;
    if (i < NN) g_deg[i] = 0;
}

// ---------------- weight fp16 transpose-pack ---------------------------------
__global__ void k_wprep(const float* __restrict__ W1, const float* __restrict__ W2) {
    int i = blockIdx.x * blockDim.x + threadIdx.x;
    if (i < 128 * 64) {
        int n = i >> 6, k2 = i & 63;
        g_W1p[i] = f2h2(W1[(2 * k2) * 128 + n], W1[(2 * k2 + 1) * 128 + n]);
    } else if (i < 128 * 64 + 64 * 64) {
        int j = i - 128 * 64;
        int n = j >> 6, k2 = j & 63;
        g_W2p[j] = f2h2(W2[(2 * k2) * 64 + n], W2[(2 * k2 + 1) * 64 + n]);
    }
}

// ---------------- tensor-core GEMM, SINGLE full-K stage, dinv epilogue -------
// LAYER 1: hs1[NN,128] = dinv[r] * (fp16(x) @ fp16(W1)),  MT=128, NOUT=128
// LAYER 2: hs2[NN,64]  = dinv[r] * (relu(a1h+b1) @ W2),   MT=128, NOUT=64
// 256 threads = 8 warps. Full K=128 staged at once (row = 64 half2 words + 4
// pad); ONE __syncthreads, then 8 k16 mma rounds. Dyn smem (128+NOUT)*ST2*4.
template<int LAYER>
__global__ __launch_bounds__(256) void k_tc(const float* __restrict__ Xsrc,
                                            const float* __restrict__ bias) {
    constexpr int NOUT = (LAYER == 1) ? 128 : 64;
    constexpr int NMT  = (LAYER == 1) ? 2 : 1;

    const unsigned* Wp  = (LAYER == 1) ? g_W1p : g_W2p;
    __half*         Out = (LAYER == 1) ? g_hs1 : g_hs2;

    extern __shared__ unsigned smem_u[];
    unsigned* Ah = smem_u;                 // 128 * ST2 words
    unsigned* Bh = smem_u + 128 * ST2;     // NOUT * ST2 words

    const int tid  = threadIdx.x;
    const int lane = tid & 31;
    const int wid  = tid >> 5;
    const int g    = lane >> 2;
    const int t4   = lane & 3;
    const int row0 = blockIdx.x * 128;
    const int warpM = (LAYER == 1) ? (wid >> 1) * 32 : wid * 16;
    const int n0    = (LAYER == 1) ? (wid & 1) * 64 : 0;

    const unsigned sAh = (unsigned)__cvta_generic_to_shared(Ah);
    const unsigned sBh = (unsigned)__cvta_generic_to_shared(Bh);
    const int l7 = lane & 7;
    const int r8 = (lane >> 3) & 1;
    const int w4 = (lane >> 4) * 4;
    unsigned aAddr[NMT];
#pragma unroll
    for (int mi = 0; mi < NMT; mi++) {
        int row = warpM + mi * 16 + l7 + r8 * 8;
        aAddr[mi] = sAh + (unsigned)((row * ST2 + w4) * 4);
    }
    unsigned bAddr[4];
    const int bw4 = ((lane >> 3) & 1) * 4;
    const int bn8 = (lane >= 16) ? 8 : 0;
#pragma unroll
    for (int nn = 0; nn < 4; nn++) {
        int nrow = n0 + nn * 16 + l7 + bn8;
        bAddr[nn] = sBh + (unsigned)((nrow * ST2 + bw4) * 4);
    }

    // ---- stage A: full 128 rows x 64 words --------------------------------
    if (LAYER == 1) {
#pragma unroll
        for (int j = 0; j < 16; j++) {
            int idx = tid + 256 * j;            // 0..4095 float4 slots (32/row)
            int r = idx >> 5, c4 = idx & 31;
            int gr = row0 + r;
            float4 v = {0.f, 0.f, 0.f, 0.f};
            if (gr < NN)
                v = ((const float4*)(Xsrc + (size_t)gr * 128))[c4];
            *(uint2*)&Ah[r * ST2 + c4 * 2] =
                make_uint2(f2h2(v.x, v.y), f2h2(v.z, v.w));
        }
    } else {
#pragma unroll
        for (int j = 0; j < 16; j++) {
            int idx = tid + 256 * j;            // 0..4095 uint2 slots (32/row)
            int r = idx >> 5, u2 = idx & 31;
            int gr = row0 + r;
            uint2 u = {0, 0};
            if (gr < NN) {
                u = ((const uint2*)(g_a1h + (size_t)gr * 128))[u2];
                float2 ba = ((const float2*)bias)[u2 * 2];
                float2 bb = ((const float2*)bias)[u2 * 2 + 1];
                float2 f0 = h2f2(u.x), f1 = h2f2(u.y);
                u.x = f2h2(fmaxf(f0.x + ba.x, 0.f), fmaxf(f0.y + ba.y, 0.f));
                u.y = f2h2(fmaxf(f1.x + bb.x, 0.f), fmaxf(f1.y + bb.y, 0.f));
            }
            *(uint2*)&Ah[r * ST2 + u2 * 2] = u;
        }
    }
    // ---- stage B: NOUT rows x 64 words ------------------------------------
#pragma unroll
    for (int j = 0; j < NOUT / 8; j++) {
        int idx = tid + 256 * j;                // uint2 slots (32/row)
        int n = idx >> 5, u2 = idx & 31;
        *(uint2*)&Bh[n * ST2 + u2 * 2] = *(const uint2*)&Wp[n * 64 + u2 * 2];
    }
    __syncthreads();

    // ---- accumulate: 8 k16 rounds, no further syncs -----------------------
    float acc[NMT][8][4];
#pragma unroll
    for (int mi = 0; mi < NMT; mi++)
#pragma unroll
        for (int ni = 0; ni < 8; ni++)
#pragma unroll
            for (int q = 0; q < 4; q++) acc[mi][ni][q] = 0.f;

#pragma unroll
    for (int kc = 0; kc < 8; kc++) {
        const unsigned koff = kc * 32;          // 8 words = 32 bytes
        unsigned ah[NMT][4];
#pragma unroll
        for (int mi = 0; mi < NMT; mi++) ldsm4(ah[mi], aAddr[mi] + koff);
#pragma unroll
        for (int nn = 0; nn < 4; nn++) {
            unsigned bh[4];
            ldsm4(bh, bAddr[nn] + koff);
#pragma unroll
            for (int p = 0; p < 2; p++) {
                int ni = nn * 2 + p;
#pragma unroll
                for (int mi = 0; mi < NMT; mi++)
                    mmaf16(acc[mi][ni], ah[mi], bh[p * 2], bh[p * 2 + 1]);
            }
        }
    }

    // ---- epilogue: dinv[r] prescale, fp16 output --------------------------
#pragma unroll
    for (int mi = 0; mi < NMT; mi++) {
#pragma unroll
        for (int ni = 0; ni < 8; ni++) {
            int r  = row0 + warpM + mi * 16 + g;
            int cc = n0 + ni * 8 + 2 * t4;
            if (r < NN) {
                float s = g_dinv[r];
                __half2 o = __floats2half2_rn(acc[mi][ni][0] * s, acc[mi][ni][1] * s);
                *((__half2*)(Out + (size_t)r * NOUT + cc)) = o;
            }
            if (r + 8 < NN) {
                float s = g_dinv[r + 8];
                __half2 o = __floats2half2_rn(acc[mi][ni][2] * s, acc[mi][ni][3] * s);
                *((__half2*)(Out + (size_t)(r + 8) * NOUT + cc)) = o;
            }
        }
    }
}

// ---------------- AGG 1: a1h[d] = dd * sum of prescaled rows -----------------
// 8-edge batches, fp16 pairwise-tree (HADD2) then fp32 merge.
__global__ void k_agg1() {
    int gw = (blockIdx.x * blockDim.x + threadIdx.x) >> 5;
    if (gw >= NN) return;
    int lane = threadIdx.x & 31;
    int o0 = g_off[gw], o1 = g_off[gw + 1];
    const uint2* base = (const uint2*)g_hs1;
    float dd = g_dinv[gw];

    uint2 sv = base[(size_t)gw * 32 + lane];
    float2 p0 = h2f2(sv.x), p1 = h2f2(sv.y);
    float a0 = p0.x, a1 = p0.y, a2 = p1.x, a3 = p1.y;

    int i = o0;
    for (; i + 8 <= o1; i += 8) {
        int s0 = g_adj[i],     s1 = g_adj[i + 1], s2 = g_adj[i + 2], s3 = g_adj[i + 3];
        int s4 = g_adj[i + 4], s5 = g_adj[i + 5], s6 = g_adj[i + 6], s7 = g_adj[i + 7];
        uint2 v0 = base[(size_t)s0 * 32 + lane];
        uint2 v1 = base[(size_t)s1 * 32 + lane];
        uint2 v2 = base[(size_t)s2 * 32 + lane];
        uint2 v3 = base[(size_t)s3 * 32 + lane];
        uint2 v4 = base[(size_t)s4 * 32 + lane];
        uint2 v5 = base[(size_t)s5 * 32 + lane];
        uint2 v6 = base[(size_t)s6 * 32 + lane];
        uint2 v7 = base[(size_t)s7 * 32 + lane];
        unsigned tx = hadd2u(hadd2u(hadd2u(v0.x, v1.x), hadd2u(v2.x, v3.x)),
                             hadd2u(hadd2u(v4.x, v5.x), hadd2u(v6.x, v7.x)));
        unsigned ty = hadd2u(hadd2u(hadd2u(v0.y, v1.y), hadd2u(v2.y, v3.y)),
                             hadd2u(hadd2u(v4.y, v5.y), hadd2u(v6.y, v7.y)));
        float2 qx = h2f2(tx), qy = h2f2(ty);
        a0 += qx.x; a1 += qx.y; a2 += qy.x; a3 += qy.y;
    }
    for (; i < o1; i++) {
        int s = g_adj[i];
        uint2 v = base[(size_t)s * 32 + lane];
        float2 q0 = h2f2(v.x), q1 = h2f2(v.y);
        a0 += q0.x; a1 += q0.y; a2 += q1.x; a3 += q1.y;
    }
    uint2 o;
    o.x = f2h2(a0 * dd, a1 * dd);
    o.y = f2h2(a2 * dd, a3 * dd);
    ((uint2*)g_a1h)[(size_t)gw * 32 + lane] = o;
}

// ---------------- AGG 2: z[d] = dd * sum of prescaled hs2 rows + b2 ----------
__global__ void k_agg2(const float* __restrict__ b2) {
    int gw = (blockIdx.x * blockDim.x + threadIdx.x) >> 5;
    if (gw >= NN) return;
    int lane = threadIdx.x & 31;
    int o0 = g_off[gw], o1 = g_off[gw + 1];
    const unsigned* base = (const unsigned*)g_hs2;
    float dd = g_dinv[gw];

    float2 p = h2f2(base[(size_t)gw * 32 + lane]);
    float a0 = p.x, a1 = p.y;

    int i = o0;
    for (; i + 8 <= o1; i += 8) {
        int s0 = g_adj[i],     s1 = g_adj[i + 1], s2 = g_adj[i + 2], s3 = g_adj[i + 3];
        int s4 = g_adj[i + 4], s5 = g_adj[i + 5], s6 = g_adj[i + 6], s7 = g_adj[i + 7];
        unsigned v0 = base[(size_t)s0 * 32 + lane];
        unsigned v1 = base[(size_t)s1 * 32 + lane];
        unsigned v2 = base[(size_t)s2 * 32 + lane];
        unsigned v3 = base[(size_t)s3 * 32 + lane];
        unsigned v4 = base[(size_t)s4 * 32 + lane];
        unsigned v5 = base[(size_t)s5 * 32 + lane];
        unsigned v6 = base[(size_t)s6 * 32 + lane];
        unsigned v7 = base[(size_t)s7 * 32 + lane];
        unsigned t = hadd2u(hadd2u(hadd2u(v0, v1), hadd2u(v2, v3)),
                            hadd2u(hadd2u(v4, v5), hadd2u(v6, v7)));
        float2 q = h2f2(t);
        a0 += q.x; a1 += q.y;
    }
    for (; i < o1; i++) {
        float2 v = h2f2(base[(size_t)g_adj[i] * 32 + lane]);
        a0 += v.x; a1 += v.y;
    }
    float2 b = ((const float2*)b2)[lane];
    __half2 oz = __floats2half2_rn(a0 * dd + b.x, a1 * dd + b.y);
    ((__half2*)g_z)[(size_t)gw * 32 + lane] = oz;
}

// ---------------- decode: 2 edges per warp (fp16 z gather) -------------------
__global__ void k_decode(const int* __restrict__ pos, const int* __restrict__ neg,
                         float* __restrict__ out) {
    int w = (blockIdx.x * blockDim.x + threadIdx.x) >> 5;
    int e0 = w * 2;
    if (e0 >= 2 * EPP) return;                 // e0 even => e0+1 < 2*EPP too
    int lane = threadIdx.x & 31;
    int a0, b0, a1, b1;
    {
        int e = e0;
        if (e < EPP) { a0 = pos[e]; b0 = pos[EPP + e]; }
        else         { a0 = neg[e - EPP]; b0 = neg[e]; }   // neg[EPP + (e-EPP)]
        e = e0 + 1;
        if (e < EPP) { a1 = pos[e]; b1 = pos[EPP + e]; }
        else         { a1 = neg[e - EPP]; b1 = neg[e]; }
    }
    const unsigned* Z = (const unsigned*)g_z;
    unsigned za0 = Z[(size_t)a0 * 32 + lane];
    unsigned zb0 = Z[(size_t)b0 * 32 + lane];
    unsigned za1 = Z[(size_t)a1 * 32 + lane];
    unsigned zb1 = Z[(size_t)b1 * 32 + lane];
    float2 xa0 = h2f2(za0), xb0 = h2f2(zb0);
    float2 xa1 = h2f2(za1), xb1 = h2f2(zb1);
    float p0 = xa0.x * xb0.x + xa0.y * xb0.y;
    float p1 = xa1.x * xb1.x + xa1.y * xb1.y;
#pragma unroll
    for (int o = 16; o > 0; o >>= 1) {
        p0 += __shfl_xor_sync(0xFFFFFFFFu, p0, o);
        p1 += __shfl_xor_sync(0xFFFFFFFFu, p1, o);
    }
    if (lane == 0) { out[e0] = p0; out[e0 + 1] = p1; }
}

// ---------------- launch ------------------------------------------------------
extern "C" void kernel_launch(void* const* d_in, const int* in_sizes, int n_in,
                              void* d_out, int out_size) {
    const float* x   = (const float*)d_in[0];
    const int*   ei  = (const int*)  d_in[1];
    const int*   pos = (const int*)  d_in[2];
    const int*   neg = (const int*)  d_in[3];
    const float* W1  = (const float*)d_in[4];
    const float* b1  = (const float*)d_in[5];
    const float* W2  = (const float*)d_in[6];
    const float* b2  = (const float*)d_in[7];
    float* out = (float*)d_out;

    const int* src = ei;
    const int* dst = ei + EE;
    const int nb_scan = (NN + 511) / 512;  // 196

    const int SMEM1 = (128 + 128) * ST2 * 4;   // 69632 bytes
    const int SMEM2 = (128 + 64) * ST2 * 4;    // 52224 bytes

    static cudaStream_t s2 = nullptr;
    static cudaEvent_t ev0 = nullptr, evD = nullptr, ev1 = nullptr, evR = nullptr;
    if (!s2) {
        cudaStreamCreateWithFlags(&s2, cudaStreamNonBlocking);
        cudaEventCreateWithFlags(&ev0, cudaEventDisableTiming);
        cudaEventCreateWithFlags(&evD, cudaEventDisableTiming);
        cudaEventCreateWithFlags(&ev1, cudaEventDisableTiming);
        cudaEventCreateWithFlags(&evR, cudaEventDisableTiming);
        cudaFuncSetAttribute(k_tc<1>, cudaFuncAttributeMaxDynamicSharedMemorySize, SMEM1);
        cudaFuncSetAttribute(k_tc<2>, cudaFuncAttributeMaxDynamicSharedMemorySize, SMEM2);
    }

    // fork: weight prep runs on s2 from the start
    cudaEventRecord(ev0, 0);
    cudaStreamWaitEvent(s2, ev0, 0);

    k_count<<<(EE / 4 + 255) / 256, 256>>>(dst);                // main
    k_wprep<<<48, 256, 0, s2>>>(W1, W2);                        // s2
    k_scanA<<<nb_scan, 512>>>();                                // main (scan+dinv)
    cudaEventRecord(evD, 0);                                    // dinv ready

    // s2: tc1 (reads dinv in epilogue -> needs evD); ev1 BEFORE reset
    cudaStreamWaitEvent(s2, evD, 0);
    k_tc<1><<<(NN + 127) / 128, 256, SMEM1, s2>>>(x, nullptr);  // s2 (MT=128)
    cudaEventRecord(ev1, s2);
    k_reset<<<(NN + 255) / 256, 256, 0, s2>>>();                // s2 (off join path)
    cudaEventRecord(evR, s2);                                   // for final join

    k_scan3<<<nb_scan, 512>>>();                                // main (fused scan2+3)
    k_fill<<<(EE / 4 + 255) / 256, 256>>>(src, dst);            // main

    // join: agg1 needs CSR (main, in-order) + hs1 (s2)
    cudaStreamWaitEvent(0, ev1, 0);

    k_agg1<<<(NN * 32 + 255) / 256, 256>>>();
    k_tc<2><<<(NN + 127) / 128, 256, SMEM2>>>(nullptr, b1);
    k_agg2<<<(NN * 32 + 255) / 256, 256>>>(b2);
    // join s2 fully before the last launch (graph capture requires no
    // unjoined forked work; reset ended long ago so this edge is free)
    cudaStreamWaitEvent(0, evR, 0);
    // 200k warps (2 edges each) = 6.4M threads = 25000 blocks
    k_decode<<<(EPP * 32 + 255) / 256, 256>>>(pos, neg, out);
}